// round 2
// baseline (speedup 1.0000x reference)
#include <cuda_runtime.h>
#include <math.h>

#define B_  32
#define P_  16384
#define D_  8
#define J_  10
#define O_  16
#define JO_ 160

// Scratch (device globals: allocation inside kernel_launch is forbidden)
__device__ float g_uhat[(size_t)B_ * P_ * JO_];  // 335 MB: u_hat[b][p][j][o]
__device__ float g_b[(size_t)B_ * P_ * J_];      // 21 MB: routing logits b[b][p][j]
__device__ float g_s[3 * B_ * JO_];              // s accumulators for 3 iterations
__device__ float g_v[B_ * JO_];                  // v[b][j][o]

// ---------------------------------------------------------------------------
// Zero the s accumulators (must happen every call: atomics accumulate)
// ---------------------------------------------------------------------------
__global__ void zero_s_kernel() {
    int i = blockIdx.x * blockDim.x + threadIdx.x;
    if (i < 3 * B_ * JO_) g_s[i] = 0.f;
}

// ---------------------------------------------------------------------------
// Pass 0: u_hat[b,p,j,o] = sum_d x[b,p,d] * W[j,p,d,o]
// Also accumulates s1[b,j,o] = (1/J) * sum_p u_hat (since softmax(0) = 1/J).
// Thread map: 160 threads = 8 b-groups(4 b) x 20 (j, o-half) groups.
// W is read straight from global; the 8 threads sharing each W quad hit L1.
// ---------------------------------------------------------------------------
#define PT0 16
__global__ __launch_bounds__(160) void pass0_kernel(const float* __restrict__ x,
                                                    const float* __restrict__ W) {
    const int t  = threadIdx.x;
    const int bg = t / 20;
    const int jg = t % 20;
    const int j  = jg >> 1;
    const int o0 = (jg & 1) * 8;
    const int b0 = bg * 4;

    float s1[32];
#pragma unroll
    for (int q = 0; q < 32; q++) s1[q] = 0.f;

    const int p0 = blockIdx.x * PT0;
    for (int pp = 0; pp < PT0; pp++) {
        const int p = p0 + pp;

        // x rows for 4 b's (8 floats each)
        float xr[4][8];
#pragma unroll
        for (int i = 0; i < 4; i++) {
            const float4* xp = (const float4*)(x + ((size_t)(b0 + i) * P_ + p) * D_);
            float4 a = xp[0], bq = xp[1];
            xr[i][0] = a.x;  xr[i][1] = a.y;  xr[i][2] = a.z;  xr[i][3] = a.w;
            xr[i][4] = bq.x; xr[i][5] = bq.y; xr[i][6] = bq.z; xr[i][7] = bq.w;
        }

        const float* wp = W + ((size_t)j * P_ + p) * (D_ * O_) + o0;
        float acc[32];
#pragma unroll
        for (int q = 0; q < 32; q++) acc[q] = 0.f;

#pragma unroll
        for (int d = 0; d < 8; d++) {
            float4 w0 = *(const float4*)(wp + d * 16);
            float4 w1 = *(const float4*)(wp + d * 16 + 4);
#pragma unroll
            for (int i = 0; i < 4; i++) {
                float xv = xr[i][d];
                acc[i*8+0] = fmaf(xv, w0.x, acc[i*8+0]);
                acc[i*8+1] = fmaf(xv, w0.y, acc[i*8+1]);
                acc[i*8+2] = fmaf(xv, w0.z, acc[i*8+2]);
                acc[i*8+3] = fmaf(xv, w0.w, acc[i*8+3]);
                acc[i*8+4] = fmaf(xv, w1.x, acc[i*8+4]);
                acc[i*8+5] = fmaf(xv, w1.y, acc[i*8+5]);
                acc[i*8+6] = fmaf(xv, w1.z, acc[i*8+6]);
                acc[i*8+7] = fmaf(xv, w1.w, acc[i*8+7]);
            }
        }

#pragma unroll
        for (int i = 0; i < 4; i++) {
            float* up = g_uhat + ((size_t)(b0 + i) * P_ + p) * JO_ + j * O_ + o0;
            *(float4*)(up)     = make_float4(acc[i*8+0], acc[i*8+1], acc[i*8+2], acc[i*8+3]);
            *(float4*)(up + 4) = make_float4(acc[i*8+4], acc[i*8+5], acc[i*8+6], acc[i*8+7]);
#pragma unroll
            for (int k = 0; k < 8; k++) s1[i*8+k] += acc[i*8+k];
        }
    }

#pragma unroll
    for (int i = 0; i < 4; i++)
#pragma unroll
        for (int k = 0; k < 8; k++)
            atomicAdd(&g_s[(b0 + i) * JO_ + j * O_ + o0 + k], s1[i*8+k] * 0.1f);
}

// ---------------------------------------------------------------------------
// Squash: v = s * sqrt(|s|^2) / (1 + |s|^2). One thread per (b,j).
// ---------------------------------------------------------------------------
__global__ void squash_kernel(int phase, float* dout) {
    int t = blockIdx.x * blockDim.x + threadIdx.x;
    if (t >= B_ * J_) return;
    const float* sp = g_s + phase * B_ * JO_ + t * O_;
    float sv[16];
    float sq = 0.f;
#pragma unroll
    for (int o = 0; o < 16; o++) { sv[o] = sp[o]; sq += sv[o] * sv[o]; }
    float scale = sqrtf(sq) / (1.f + sq);
    float* op = dout ? (dout + t * O_) : (g_v + t * O_);
#pragma unroll
    for (int o = 0; o < 16; o++) op[o] = sv[o] * scale;
}

// ---------------------------------------------------------------------------
// Fused routing pass. One warp per (b, p-range); for each p:
//   u = u_hat[b,p,:,:]               (5 coalesced 128B loads, lanes <-> (j,o))
//   uv[j] = u . v_prev               (16-lane shfl reductions)
//   PASS==1: b := uv (store)   PASS==2: b := b_old + uv (load)
//   c = softmax_j(b)                 (warp softmax over 10 lanes)
//   s_acc += c[j] * u                (reg accumulators, block-reduced at end)
// ---------------------------------------------------------------------------
template <int PASS>
__global__ __launch_bounds__(256) void route_kernel() {
    const int warpId = threadIdx.x >> 5;
    const int lane   = threadIdx.x & 31;
    const int gw     = blockIdx.x * 8 + warpId;   // 0..16383
    const int b      = gw >> 9;                   // 512 warps per batch element
    const int pbase  = (gw & 511) << 5;           // 32 p's per warp

    __shared__ float c_s[8][16];
    __shared__ float red_s[8][JO_];

    float vreg[5];
#pragma unroll
    for (int r = 0; r < 5; r++) vreg[r] = g_v[b * JO_ + r * 32 + lane];

    float sacc[5] = {0.f, 0.f, 0.f, 0.f, 0.f};

    for (int pi = 0; pi < 32; pi++) {
        const int p = pbase + pi;
        const float* up = g_uhat + ((size_t)b * P_ + p) * JO_;

        float u[5];
#pragma unroll
        for (int r = 0; r < 5; r++) u[r] = up[r * 32 + lane];

        // uv[j] = sum_o u[j,o]*v[j,o]; round r covers j = {2r, 2r+1}
#pragma unroll
        for (int r = 0; r < 5; r++) {
            float red = u[r] * vreg[r];
            red += __shfl_xor_sync(0xffffffffu, red, 1);
            red += __shfl_xor_sync(0xffffffffu, red, 2);
            red += __shfl_xor_sync(0xffffffffu, red, 4);
            red += __shfl_xor_sync(0xffffffffu, red, 8);
            if ((lane & 15) == 0) c_s[warpId][2 * r + (lane >> 4)] = red;
        }
        __syncwarp();

        float bj = -1e30f;
        if (lane < J_) {
            bj = c_s[warpId][lane];
            float* bp = g_b + ((size_t)b * P_ + p) * J_ + lane;
            if (PASS == 2) bj += *bp;   // b_old + uv
            else           *bp = bj;    // first update: b was 0
        }

        // softmax over j (10 valid lanes; others hold -inf / 0)
        float mx = bj;
#pragma unroll
        for (int m = 16; m >= 1; m >>= 1)
            mx = fmaxf(mx, __shfl_xor_sync(0xffffffffu, mx, m));
        float e = (lane < J_) ? __expf(bj - mx) : 0.f;
        float sm = e;
#pragma unroll
        for (int m = 16; m >= 1; m >>= 1)
            sm += __shfl_xor_sync(0xffffffffu, sm, m);
        float c = __fdividef(e, sm);

        __syncwarp();
        if (lane < J_) c_s[warpId][lane] = c;
        __syncwarp();

#pragma unroll
        for (int r = 0; r < 5; r++)
            sacc[r] = fmaf(c_s[warpId][(r * 32 + lane) >> 4], u[r], sacc[r]);
        __syncwarp();
    }

    // block reduction (all 8 warps share the same b), then one atomic per (j,o)
#pragma unroll
    for (int r = 0; r < 5; r++) red_s[warpId][r * 32 + lane] = sacc[r];
    __syncthreads();
    const int t = threadIdx.x;
    if (t < JO_) {
        float sum = 0.f;
#pragma unroll
        for (int w = 0; w < 8; w++) sum += red_s[w][t];
        const int bb = (blockIdx.x * 8) >> 9;
        atomicAdd(&g_s[PASS * B_ * JO_ + bb * JO_ + t], sum);
    }
}

// ---------------------------------------------------------------------------
// Launch: zero -> pass0(+s1) -> squash(v1) -> route1(+s2) -> squash(v2)
//              -> route2(+s3) -> squash -> d_out
// ---------------------------------------------------------------------------
extern "C" void kernel_launch(void* const* d_in, const int* in_sizes, int n_in,
                              void* d_out, int out_size) {
    const float* x = (const float*)d_in[0];
    const float* W = (const float*)d_in[1];
    if (n_in >= 2 && in_sizes[0] > in_sizes[1]) {  // robustness to input order
        x = (const float*)d_in[1];
        W = (const float*)d_in[0];
    }
    float* out = (float*)d_out;

    zero_s_kernel<<<60, 256>>>();
    pass0_kernel<<<P_ / PT0, 160>>>(x, W);
    squash_kernel<<<2, 160>>>(0, nullptr);
    route_kernel<1><<<2048, 256>>>();
    squash_kernel<<<2, 160>>>(1, nullptr);
    route_kernel<2><<<2048, 256>>>();
    squash_kernel<<<2, 160>>>(2, out);
}

// round 3
// speedup vs baseline: 1.7998x; 1.7998x over previous
#include <cuda_runtime.h>
#include <cuda_fp16.h>
#include <math.h>

#define B_  32
#define P_  16384
#define J_  10
#define O_  16
#define JO_ 160

// Scratch (device globals: no allocation allowed in kernel_launch)
__device__ unsigned short g_uh[(size_t)B_ * P_ * JO_]; // 168MB fp16 u_hat[b][p][jo]
__device__ float g_b[(size_t)B_ * P_ * J_];            // 21MB routing logits
__device__ float g_s[3 * B_ * JO_];                    // s accumulators
__device__ float g_v[B_ * JO_];                        // v[b][j][o]

// ---------------------------------------------------------------------------
__global__ void zero_s_kernel() {
    int i = blockIdx.x * blockDim.x + threadIdx.x;
    if (i < 3 * B_ * JO_) g_s[i] = 0.f;
}

// ---------------------------------------------------------------------------
// Pass 0: u_hat[b,p,jo] = sum_d x[b,p,d] * W[j,p,d,o]   (fp16 out)
// Warp = (p-group of 8, b-half of 16). Lane owns 5 jo columns (jo = r*32+lane);
// W held in 40 registers (reused across 16 b), x broadcast via shfl.
// s1 = 0.1 * sum_p u accumulated in 80 regs, block-reduced in smem, then
// one atomicAdd sweep per block (512 hits/address — negligible).
// ---------------------------------------------------------------------------
#define NP 8
__global__ __launch_bounds__(256) void pass0_kernel(const float* __restrict__ x,
                                                    const float* __restrict__ W) {
    const int w    = threadIdx.x >> 5;
    const int lane = threadIdx.x & 31;
    const int gw   = blockIdx.x * 8 + w;     // 4096 warps
    const int pg   = gw >> 1;                // 2048 p-groups
    const int b0   = (gw & 1) * 16;          // b-half
    const int p0   = pg * NP;

    __shared__ float s1red[B_ * JO_];        // 20KB
    for (int i = threadIdx.x; i < B_ * JO_; i += 256) s1red[i] = 0.f;
    __syncthreads();

    float s1[16][5];
#pragma unroll
    for (int bb = 0; bb < 16; bb++)
#pragma unroll
        for (int r = 0; r < 5; r++) s1[bb][r] = 0.f;

    __half* uh = reinterpret_cast<__half*>(g_uh);

    for (int pp = 0; pp < NP; pp++) {
        const int p = p0 + pp;

        float wreg[5][8];
#pragma unroll
        for (int r = 0; r < 5; r++) {
            const int jo = r * 32 + lane;
            const float* wp = W + ((size_t)(jo >> 4) * P_ + p) * 128 + (jo & 15);
#pragma unroll
            for (int d = 0; d < 8; d++) wreg[r][d] = __ldg(wp + d * 16);
        }

        // lane l holds float4 part (l&1) of x-row for b = b0 + (l>>1)
        const float4 xq = *(const float4*)(x + ((size_t)(b0 + (lane >> 1)) * P_ + p) * 8
                                             + (lane & 1) * 4);

#pragma unroll
        for (int bb = 0; bb < 16; bb++) {
            float acc[5] = {0.f, 0.f, 0.f, 0.f, 0.f};
#pragma unroll
            for (int d = 0; d < 8; d++) {
                const float xv = __shfl_sync(0xffffffffu,
                                             ((const float*)&xq)[d & 3],
                                             (bb << 1) | (d >> 2));
#pragma unroll
                for (int r = 0; r < 5; r++) acc[r] = fmaf(xv, wreg[r][d], acc[r]);
            }
            __half* up = uh + ((size_t)(b0 + bb) * P_ + p) * JO_;
#pragma unroll
            for (int r = 0; r < 5; r++) {
                up[r * 32 + lane] = __float2half(acc[r]);
                s1[bb][r] += acc[r];
            }
        }
    }

    // block s1 reduction: 4 phases; active warp pair (bh=0,1) writes disjoint b
    for (int k = 0; k < 4; k++) {
        if ((w >> 1) == k) {
#pragma unroll
            for (int bb = 0; bb < 16; bb++)
#pragma unroll
                for (int r = 0; r < 5; r++)
                    s1red[(b0 + bb) * JO_ + r * 32 + lane] += s1[bb][r];
        }
        __syncthreads();
    }
    for (int i = threadIdx.x; i < B_ * JO_; i += 256)
        atomicAdd(&g_s[i], s1red[i] * 0.1f);
}

// ---------------------------------------------------------------------------
// Squash: v = s * sqrt(|s|^2) / (1 + |s|^2). One thread per (b,j).
// ---------------------------------------------------------------------------
__global__ void squash_kernel(int phase, float* dout) {
    int t = blockIdx.x * blockDim.x + threadIdx.x;
    if (t >= B_ * J_) return;
    const float* sp = g_s + phase * B_ * JO_ + t * O_;
    float sv[16], sq = 0.f;
#pragma unroll
    for (int o = 0; o < 16; o++) { sv[o] = sp[o]; sq += sv[o] * sv[o]; }
    float scale = sqrtf(sq) / (1.f + sq);
    float* op = dout ? (dout + t * O_) : (g_v + t * O_);
#pragma unroll
    for (int o = 0; o < 16; o++) op[o] = sv[o] * scale;
}

// ---------------------------------------------------------------------------
// Fused routing pass, 2 p's per warp per iteration on half2 units.
// unit i = r*32+lane in [0,160): psub = i/80, half-index h = (2i)%160,
// j = h/16. Group of 8 consecutive units = one (p,j) dot -> 3 xor-shfls.
// Softmax for both p's at once in the two 16-lane halves (4 shfls each).
// ---------------------------------------------------------------------------
template <int PASS>
__global__ __launch_bounds__(256) void route_kernel() {
    const int w    = threadIdx.x >> 5;
    const int lane = threadIdx.x & 31;
    const int gw   = blockIdx.x * 8 + w;      // 16384 warps
    const int b    = gw >> 9;                 // 512 warps per batch elem
    const int pbase = (gw & 511) << 5;        // 32 p per warp

    __shared__ float gbuf[8][32];
    __shared__ float cbuf[8][32];
    __shared__ float red[8][JO_];

    float2 v2[5];
    int cidx[5], joidx[5], ps[5];
#pragma unroll
    for (int r = 0; r < 5; r++) {
        const int i = r * 32 + lane;
        ps[r] = i / 80;
        const int h = (2 * i) % 160;
        joidx[r] = h;
        cidx[r]  = ps[r] * 16 + (h >> 4);
        v2[r] = make_float2(g_v[b * JO_ + h], g_v[b * JO_ + h + 1]);
    }

    float2 sacc[5];
#pragma unroll
    for (int r = 0; r < 5; r++) sacc[r] = make_float2(0.f, 0.f);

    const unsigned* ub = reinterpret_cast<const unsigned*>(g_uh)
                         + ((size_t)b * P_ + pbase) * 80;
    const bool valid = (lane & 15) < J_;

    for (int it = 0; it < 16; it++) {
        const int p = pbase + it * 2 + (lane >> 4);
        float* bp = g_b + ((size_t)b * P_ + p) * J_ + (lane & 15);
        float bold = 0.f;
        if (PASS == 2 && valid) bold = __ldg(bp);

        const unsigned* up = ub + it * 160;
        float2 uf[5];
#pragma unroll
        for (int r = 0; r < 5; r++) {
            const unsigned uu = __ldg(up + r * 32 + lane);
            uf[r] = __half22float2(*reinterpret_cast<const __half2*>(&uu));
        }

        // uv dot products: 8-lane group reductions
#pragma unroll
        for (int r = 0; r < 5; r++) {
            float dv = fmaf(uf[r].x, v2[r].x, uf[r].y * v2[r].y);
            dv += __shfl_xor_sync(0xffffffffu, dv, 1);
            dv += __shfl_xor_sync(0xffffffffu, dv, 2);
            dv += __shfl_xor_sync(0xffffffffu, dv, 4);
            if ((lane & 7) == 0) gbuf[w][r * 4 + (lane >> 3)] = dv;
        }
        __syncwarp();

        float bj = -1e30f;
        if (valid) {
            bj = gbuf[w][(lane >> 4) * 10 + (lane & 15)] + bold;
            if (PASS == 1) *bp = bj;
        }

        // softmax over j within each 16-lane half (one p per half)
        float mx = bj;
#pragma unroll
        for (int m = 8; m >= 1; m >>= 1)
            mx = fmaxf(mx, __shfl_xor_sync(0xffffffffu, mx, m));
        const float e = valid ? __expf(bj - mx) : 0.f;
        float sm = e;
#pragma unroll
        for (int m = 8; m >= 1; m >>= 1)
            sm += __shfl_xor_sync(0xffffffffu, sm, m);
        const float c = __fdividef(e, sm);
        if (valid) cbuf[w][(lane >> 4) * 16 + (lane & 15)] = c;
        __syncwarp();

#pragma unroll
        for (int r = 0; r < 5; r++) {
            const float cc = cbuf[w][cidx[r]];
            sacc[r].x = fmaf(cc, uf[r].x, sacc[r].x);
            sacc[r].y = fmaf(cc, uf[r].y, sacc[r].y);
        }
        __syncwarp();
    }

    // fold the two p-halves together into red[w][jo]
#pragma unroll
    for (int r = 0; r < 5; r++)
        if (ps[r] == 0) { red[w][joidx[r]] = sacc[r].x; red[w][joidx[r] + 1] = sacc[r].y; }
    __syncwarp();
#pragma unroll
    for (int r = 0; r < 5; r++)
        if (ps[r] == 1) { red[w][joidx[r]] += sacc[r].x; red[w][joidx[r] + 1] += sacc[r].y; }
    __syncthreads();

    if (threadIdx.x < JO_) {
        float s = 0.f;
#pragma unroll
        for (int k = 0; k < 8; k++) s += red[k][threadIdx.x];
        atomicAdd(&g_s[PASS * B_ * JO_ + b * JO_ + threadIdx.x], s);
    }
}

// ---------------------------------------------------------------------------
extern "C" void kernel_launch(void* const* d_in, const int* in_sizes, int n_in,
                              void* d_out, int out_size) {
    const float* x = (const float*)d_in[0];
    const float* W = (const float*)d_in[1];
    if (n_in >= 2 && in_sizes[0] > in_sizes[1]) {
        x = (const float*)d_in[1];
        W = (const float*)d_in[0];
    }
    float* out = (float*)d_out;

    zero_s_kernel<<<60, 256>>>();
    pass0_kernel<<<512, 256>>>(x, W);
    squash_kernel<<<2, 160>>>(0, nullptr);
    route_kernel<1><<<2048, 256>>>();
    squash_kernel<<<2, 160>>>(1, nullptr);
    route_kernel<2><<<2048, 256>>>();
    squash_kernel<<<2, 160>>>(2, out);
}

// round 4
// speedup vs baseline: 1.8718x; 1.0400x over previous
#include <cuda_runtime.h>
#include <cuda_fp16.h>
#include <math.h>

#define B_  32
#define P_  16384
#define J_  10
#define O_  16
#define JO_ 160

// Scratch (device globals: no allocation allowed in kernel_launch)
__device__ unsigned short g_uh[(size_t)B_ * P_ * JO_]; // 168MB fp16 u_hat[b][p][jo]
__device__ float g_b[(size_t)B_ * P_ * J_];            // 21MB routing logits
__device__ float g_s[3 * B_ * JO_];                    // s accumulators
__device__ unsigned short g_vh[B_ * JO_];              // v in fp16 (packed by squash)

// ---------------------------------------------------------------------------
__global__ void zero_s_kernel() {
    int i = blockIdx.x * blockDim.x + threadIdx.x;
    if (i < 3 * B_ * JO_) g_s[i] = 0.f;
}

// ---------------------------------------------------------------------------
// Pass 0: u_hat[b,p,jo] = sum_d x[b,p,d] * W[j,p,d,o]   (fp16 out)
// Warp = (p-group of 8, b-octet of 8). Lane owns jo = r*32+lane for 8 b's.
// 4 octet warps in a block share each p-range -> W loads hit L1.
// s1 accumulated in 40 regs, block-reduced in smem (2 phases), atomics once.
// ---------------------------------------------------------------------------
#define NP 8
__global__ __launch_bounds__(256) void pass0_kernel(const float* __restrict__ x,
                                                    const float* __restrict__ W) {
    const int w    = threadIdx.x >> 5;
    const int lane = threadIdx.x & 31;
    const int pgl  = w >> 2;                     // p-subgroup in block (0/1)
    const int oct  = w & 3;                      // b-octet
    const int pg   = blockIdx.x * 2 + pgl;       // 2048 p-groups
    const int b0   = oct * 8;
    const int p0   = pg * NP;

    __shared__ float s1red[B_ * JO_];            // 20KB
    for (int i = threadIdx.x; i < B_ * JO_; i += 256) s1red[i] = 0.f;
    __syncthreads();

    float s1[8][5];
#pragma unroll
    for (int bb = 0; bb < 8; bb++)
#pragma unroll
        for (int r = 0; r < 5; r++) s1[bb][r] = 0.f;

    __half* uh = reinterpret_cast<__half*>(g_uh);

    for (int pp = 0; pp < NP; pp++) {
        const int p = p0 + pp;

        float wreg[5][8];
#pragma unroll
        for (int r = 0; r < 5; r++) {
            const int jo = r * 32 + lane;
            const float* wp = W + ((size_t)(jo >> 4) * P_ + p) * 128 + (jo & 15);
#pragma unroll
            for (int d = 0; d < 8; d++) wreg[r][d] = __ldg(wp + d * 16);
        }

        // lanes (ℓ&15): b_local = (ℓ&15)>>1, half = ℓ&1
        const int ll = lane & 15;
        const float4 xq = *(const float4*)(x + ((size_t)(b0 + (ll >> 1)) * P_ + p) * 8
                                             + (ll & 1) * 4);

#pragma unroll
        for (int bb = 0; bb < 8; bb++) {
            float acc[5] = {0.f, 0.f, 0.f, 0.f, 0.f};
#pragma unroll
            for (int d = 0; d < 8; d++) {
                const float xv = __shfl_sync(0xffffffffu,
                                             ((const float*)&xq)[d & 3],
                                             (bb << 1) | (d >> 2));
#pragma unroll
                for (int r = 0; r < 5; r++) acc[r] = fmaf(xv, wreg[r][d], acc[r]);
            }
            __half* up = uh + ((size_t)(b0 + bb) * P_ + p) * JO_;
#pragma unroll
            for (int r = 0; r < 5; r++) {
                up[r * 32 + lane] = __float2half(acc[r]);
                s1[bb][r] += acc[r];
            }
        }
    }

    // block s1 reduction: 2 phases over p-subgroups; octets disjoint in b
    for (int k = 0; k < 2; k++) {
        if (pgl == k) {
#pragma unroll
            for (int bb = 0; bb < 8; bb++)
#pragma unroll
                for (int r = 0; r < 5; r++)
                    s1red[(b0 + bb) * JO_ + r * 32 + lane] += s1[bb][r];
        }
        __syncthreads();
    }
    for (int i = threadIdx.x; i < B_ * JO_; i += 256)
        atomicAdd(&g_s[i], s1red[i] * 0.1f);
}

// ---------------------------------------------------------------------------
// Squash: v = s * sqrt(|s|^2) / (1 + |s|^2). One thread per (b,j).
// Phases 0,1 -> g_vh (fp16). Phase 2 -> d_out (fp32).
// ---------------------------------------------------------------------------
__global__ void squash_kernel(int phase, float* dout) {
    int t = blockIdx.x * blockDim.x + threadIdx.x;
    if (t >= B_ * J_) return;
    const float* sp = g_s + phase * B_ * JO_ + t * O_;
    float sv[16], sq = 0.f;
#pragma unroll
    for (int o = 0; o < 16; o++) { sv[o] = sp[o]; sq += sv[o] * sv[o]; }
    float scale = sqrtf(sq) / (1.f + sq);
    if (dout) {
        float* op = dout + t * O_;
#pragma unroll
        for (int o = 0; o < 16; o++) op[o] = sv[o] * scale;
    } else {
        __half* op = reinterpret_cast<__half*>(g_vh) + t * O_;
#pragma unroll
        for (int o = 0; o < 16; o++) op[o] = __float2half(sv[o] * scale);
    }
}

// ---------------------------------------------------------------------------
// Fused routing pass, 8 p's per warp-iteration via uint4 (8 fp16) loads.
// Unit u = r*32+lane in [0,160): p_sub = u/20, q20 = u%20 -> (j=q20>>1, oh=q20&1),
// lane's uint4 = 8 contiguous jo halves [q20*8 .. q20*8+8).
// Dot: 8-wide local fp32 dot + one xor-1 shfl (pair = same r, adjacent lanes).
// Softmax: 32 owner lanes, quad = same p_sub, j striped by lane&3.
// ---------------------------------------------------------------------------
template <int PASS>
__global__ __launch_bounds__(256) void route_kernel() {
    const int w     = threadIdx.x >> 5;
    const int lane  = threadIdx.x & 31;
    const int gw    = blockIdx.x * 8 + w;     // 16384 warps
    const int b     = gw >> 9;
    const int pbase = (gw & 511) << 5;        // 32 p per warp

    __shared__ float gbuf[8][80];
    __shared__ float cbuf[8][80];
    __shared__ float red[8][JO_];

    int q20[5], psub[5];
#pragma unroll
    for (int r = 0; r < 5; r++) {
        const int u = r * 32 + lane;
        psub[r] = u / 20;
        q20[r]  = u % 20;
    }

    // v (fp16) for this lane's units: uint4 = 8 halves at jo = q20*8
    uint4 v4[5];
#pragma unroll
    for (int r = 0; r < 5; r++)
        v4[r] = *(const uint4*)(g_vh + b * JO_ + q20[r] * 8);

    float2 sacc[5][4];
#pragma unroll
    for (int r = 0; r < 5; r++)
#pragma unroll
        for (int k = 0; k < 4; k++) sacc[r][k] = make_float2(0.f, 0.f);

    // softmax ownership: quad = p_sub (lane>>2), k4 = lane&3
    const int sm_ps = lane >> 2;
    const int k4    = lane & 3;
    const int nj    = (k4 < 2) ? 3 : 2;       // j in {k4, k4+4, k4+8?}

    for (int it = 0; it < 4; it++) {
        const int p0 = pbase + it * 8;
        const uint4* up = (const uint4*)(g_uh + ((size_t)b * P_ + p0) * JO_);

        uint4 u4[5];
#pragma unroll
        for (int r = 0; r < 5; r++) u4[r] = __ldg(up + r * 32 + lane);

        // dots: per unit local 8-wide fp32 dot, then pair shfl
#pragma unroll
        for (int r = 0; r < 5; r++) {
            const __half2* uh2 = (const __half2*)&u4[r];
            const __half2* vh2 = (const __half2*)&v4[r];
            float dv = 0.f;
#pragma unroll
            for (int k = 0; k < 4; k++) {
                const float2 uf = __half22float2(uh2[k]);
                const float2 vf = __half22float2(vh2[k]);
                dv = fmaf(uf.x, vf.x, dv);
                dv = fmaf(uf.y, vf.y, dv);
            }
            dv += __shfl_xor_sync(0xffffffffu, dv, 1);
            if (!(lane & 1)) gbuf[w][(r * 32 + lane) >> 1] = dv;
        }
        __syncwarp();

        // softmax over j for 8 p's (owner lanes)
        {
            float lg[3];
            float mx = -1e30f;
            float* bp = g_b + ((size_t)b * P_ + p0 + sm_ps) * J_;
#pragma unroll
            for (int i = 0; i < 3; i++) {
                if (i < nj) {
                    const int j = k4 + i * 4;
                    float t = gbuf[w][sm_ps * 10 + j];
                    if (PASS == 2) t += __ldg(bp + j);
                    else           bp[j] = t;       // b was 0
                    lg[i] = t;
                    mx = fmaxf(mx, t);
                } else lg[i] = -1e30f;
            }
            mx = fmaxf(mx, __shfl_xor_sync(0xffffffffu, mx, 1));
            mx = fmaxf(mx, __shfl_xor_sync(0xffffffffu, mx, 2));
            float e[3], sm = 0.f;
#pragma unroll
            for (int i = 0; i < 3; i++) {
                e[i] = (i < nj) ? __expf(lg[i] - mx) : 0.f;
                sm += e[i];
            }
            sm += __shfl_xor_sync(0xffffffffu, sm, 1);
            sm += __shfl_xor_sync(0xffffffffu, sm, 2);
            const float inv = __fdividef(1.f, sm);
#pragma unroll
            for (int i = 0; i < 3; i++)
                if (i < nj) cbuf[w][sm_ps * 10 + k4 + i * 4] = e[i] * inv;
        }
        __syncwarp();

        // accumulate c * u
#pragma unroll
        for (int r = 0; r < 5; r++) {
            const float c = cbuf[w][(r * 32 + lane) >> 1];
            const __half2* uh2 = (const __half2*)&u4[r];
#pragma unroll
            for (int k = 0; k < 4; k++) {
                const float2 uf = __half22float2(uh2[k]);
                sacc[r][k].x = fmaf(c, uf.x, sacc[r][k].x);
                sacc[r][k].y = fmaf(c, uf.y, sacc[r][k].y);
            }
        }
        __syncwarp();
    }

    // fold sacc into red[w][jo] in 8 p_sub phases (conflict-free per phase)
    for (int i = lane; i < JO_; i += 32) red[w][i] = 0.f;
    __syncwarp();
#pragma unroll
    for (int ph = 0; ph < 8; ph++) {
#pragma unroll
        for (int r = 0; r < 5; r++) {
            if (psub[r] == ph) {
#pragma unroll
                for (int k = 0; k < 4; k++) {
                    red[w][q20[r] * 8 + 2 * k]     += sacc[r][k].x;
                    red[w][q20[r] * 8 + 2 * k + 1] += sacc[r][k].y;
                }
            }
        }
        __syncwarp();
    }
    __syncthreads();

    if (threadIdx.x < JO_) {
        float s = 0.f;
#pragma unroll
        for (int k = 0; k < 8; k++) s += red[k][threadIdx.x];
        atomicAdd(&g_s[PASS * B_ * JO_ + b * JO_ + threadIdx.x], s);
    }
}

// ---------------------------------------------------------------------------
extern "C" void kernel_launch(void* const* d_in, const int* in_sizes, int n_in,
                              void* d_out, int out_size) {
    const float* x = (const float*)d_in[0];
    const float* W = (const float*)d_in[1];
    if (n_in >= 2 && in_sizes[0] > in_sizes[1]) {
        x = (const float*)d_in[1];
        W = (const float*)d_in[0];
    }
    float* out = (float*)d_out;

    zero_s_kernel<<<60, 256>>>();
    pass0_kernel<<<1024, 256>>>(x, W);
    squash_kernel<<<2, 160>>>(0, nullptr);
    route_kernel<1><<<2048, 256>>>();
    squash_kernel<<<2, 160>>>(1, nullptr);
    route_kernel<2><<<2048, 256>>>();
    squash_kernel<<<2, 160>>>(2, out);
}

// round 5
// speedup vs baseline: 2.1037x; 1.1239x over previous
#include <cuda_runtime.h>
#include <cuda_fp16.h>
#include <math.h>

#define B_  32
#define P_  16384
#define J_  10
#define O_  16
#define JO_ 160

// Scratch (device globals: no allocation allowed in kernel_launch)
__device__ unsigned short g_uh[(size_t)B_ * P_ * JO_]; // 168MB fp16 u_hat[b][p][jo]
__device__ float g_s[3 * B_ * JO_];                    // s accumulators
__device__ float g_vf[B_ * JO_];                       // v1 stash (fp32)
__device__ unsigned short g_vh[B_ * JO_];              // current dot-vector (fp16)

// ---------------------------------------------------------------------------
__global__ void zero_s_kernel() {
    int i = blockIdx.x * blockDim.x + threadIdx.x;
    if (i < 3 * B_ * JO_) g_s[i] = 0.f;
}

// ---------------------------------------------------------------------------
// Pass 0: u_hat[b,p,jo] = sum_d x[b,p,d] * W[j,p,d,o]   (fp16 out)
// Warp = (p-subgroup, b-octet). Lane owns jo = r*32+lane. W d-streamed (5 regs).
// s1 partials go straight into a per-warp smem slice (no races, no extra regs),
// block-reduced at the end into global atomics.
// ---------------------------------------------------------------------------
#define NP 8
__global__ __launch_bounds__(256) void pass0_kernel(const float* __restrict__ x,
                                                    const float* __restrict__ W) {
    const int w    = threadIdx.x >> 5;
    const int lane = threadIdx.x & 31;
    const int oct  = w & 3;                      // b-octet
    const int pg   = blockIdx.x * 2 + (w >> 2);  // 2048 p-groups
    const int b0   = oct * 8;
    const int p0   = pg * NP;

    __shared__ float s1sm[8][8 * JO_];           // per-warp slices, 40KB
    float* s1w = s1sm[w];
    for (int i = lane; i < 8 * JO_; i += 32) s1w[i] = 0.f;
    __syncwarp();

    __half* uh = reinterpret_cast<__half*>(g_uh);

    for (int pp = 0; pp < NP; pp++) {
        const int p = p0 + pp;

        // lane ll=lane&15 holds float4 part (ll&1) of x-row for b = b0 + (ll>>1)
        const int ll = lane & 15;
        const float4 xq = *(const float4*)(x + ((size_t)(b0 + (ll >> 1)) * P_ + p) * 8
                                             + (ll & 1) * 4);

        float acc[8][5];
#pragma unroll
        for (int bb = 0; bb < 8; bb++)
#pragma unroll
            for (int r = 0; r < 5; r++) acc[bb][r] = 0.f;

#pragma unroll
        for (int d = 0; d < 8; d++) {
            float wv[5];
#pragma unroll
            for (int r = 0; r < 5; r++) {
                const int jo = r * 32 + lane;
                wv[r] = __ldg(W + ((size_t)(jo >> 4) * P_ + p) * 128 + d * 16 + (jo & 15));
            }
#pragma unroll
            for (int bb = 0; bb < 8; bb++) {
                const float xv = __shfl_sync(0xffffffffu,
                                             ((const float*)&xq)[d & 3],
                                             (bb << 1) | (d >> 2));
#pragma unroll
                for (int r = 0; r < 5; r++) acc[bb][r] = fmaf(xv, wv[r], acc[bb][r]);
            }
        }

#pragma unroll
        for (int bb = 0; bb < 8; bb++) {
            __half* up = uh + ((size_t)(b0 + bb) * P_ + p) * JO_;
            float*  sw = s1w + bb * JO_;
#pragma unroll
            for (int r = 0; r < 5; r++) {
                up[r * 32 + lane] = __float2half(acc[bb][r]);
                sw[r * 32 + lane] += acc[bb][r];
            }
        }
    }

    __syncthreads();
    // fold the 8 per-warp slices -> global s1 (slot 0), scaled by 1/J
    for (int i = threadIdx.x; i < B_ * JO_; i += 256) {
        const int b  = i / JO_, jo = i % JO_;
        const int o1 = b >> 3, bb = b & 7;
        const float sum = s1sm[o1][bb * JO_ + jo] + s1sm[o1 + 4][bb * JO_ + jo];
        atomicAdd(&g_s[i], sum * 0.1f);
    }
}

// ---------------------------------------------------------------------------
// Squash: v = s * sqrt(|s|^2) / (1 + |s|^2). One thread per (b,j).
// phase 0: v1 -> g_vh (fp16) and g_vf (fp32 stash)
// phase 1: v2 -> g_vh = fp16(v1 + v2)    [logit linearity: b = u·(v1+v2)]
// phase 2: v3 -> d_out (fp32)
// ---------------------------------------------------------------------------
__global__ void squash_kernel(int phase, float* dout) {
    int t = blockIdx.x * blockDim.x + threadIdx.x;
    if (t >= B_ * J_) return;
    const float* sp = g_s + phase * B_ * JO_ + t * O_;
    float sv[16], sq = 0.f;
#pragma unroll
    for (int o = 0; o < 16; o++) { sv[o] = sp[o]; sq += sv[o] * sv[o]; }
    const float scale = sqrtf(sq) / (1.f + sq);
    __half* vh = reinterpret_cast<__half*>(g_vh) + t * O_;
    if (phase == 0) {
#pragma unroll
        for (int o = 0; o < 16; o++) {
            const float v = sv[o] * scale;
            g_vf[t * O_ + o] = v;
            vh[o] = __float2half(v);
        }
    } else if (phase == 1) {
#pragma unroll
        for (int o = 0; o < 16; o++)
            vh[o] = __float2half(g_vf[t * O_ + o] + sv[o] * scale);
    } else {
#pragma unroll
        for (int o = 0; o < 16; o++) dout[t * O_ + o] = sv[o] * scale;
    }
}

// ---------------------------------------------------------------------------
// Fused routing pass: 4 p per iteration, prefetched uint2 (4 fp16) loads.
// Unit u = r*32+lane in [0,160): covers halves H=4u..4u+3 of the 4p block,
// p_sub = u/40, j = (u%40)/4. j-groups are lane QUADS -> 2 shfls per dot.
// Softmax: 8-lane octets, one p_sub each, j striped by lane&7. No g_b at all.
// ---------------------------------------------------------------------------
template <int SLOT>
__global__ __launch_bounds__(256) void route_kernel() {
    const int w     = threadIdx.x >> 5;
    const int lane  = threadIdx.x & 31;
    const int gw    = blockIdx.x * 8 + w;     // 16384 warps
    const int b     = gw >> 9;
    const int pbase = (gw & 511) << 5;        // 32 p per warp

    __shared__ float gbuf[8][40];
    __shared__ float cbuf[8][40];
    __shared__ float red[8][JO_];

    int q[5], slot[5], psub[5];
#pragma unroll
    for (int r = 0; r < 5; r++) {
        const int u = r * 32 + lane;
        psub[r] = u / 40;
        q[r]    = (4 * u) % 160;              // starting jo of this unit
        slot[r] = u >> 2;                     // == psub*10 + j
    }

    uint2 v2[5];
#pragma unroll
    for (int r = 0; r < 5; r++)
        v2[r] = *(const uint2*)(g_vh + b * JO_ + q[r]);

    float sacc[5][4];
#pragma unroll
    for (int r = 0; r < 5; r++)
#pragma unroll
        for (int k = 0; k < 4; k++) sacc[r][k] = 0.f;

    const uint2* up = (const uint2*)(g_uh + ((size_t)b * P_ + pbase) * JO_);

    // softmax ownership: octet = p_sub (lane>>3), k8 = lane&7
    const int sm_ps = lane >> 3;
    const int k8    = lane & 7;
    const int nj    = (k8 < 2) ? 2 : 1;       // j in {k8, k8+8?}

    uint2 ucur[5], unxt[5];
#pragma unroll
    for (int r = 0; r < 5; r++) ucur[r] = __ldg(up + r * 32 + lane);

    for (int it = 0; it < 8; it++) {
        if (it < 7) {
#pragma unroll
            for (int r = 0; r < 5; r++)
                unxt[r] = __ldg(up + (it + 1) * 160 + r * 32 + lane);
        }

        // dots: per-unit 4-wide fp16 product, fp32 quad reduction
#pragma unroll
        for (int r = 0; r < 5; r++) {
            const __half2* uh2 = (const __half2*)&ucur[r];
            const __half2* vh2 = (const __half2*)&v2[r];
            const __half2 t = __hfma2(uh2[0], vh2[0], __hmul2(uh2[1], vh2[1]));
            float dv = __low2float(t) + __high2float(t);
            dv += __shfl_xor_sync(0xffffffffu, dv, 1);
            dv += __shfl_xor_sync(0xffffffffu, dv, 2);
            if ((lane & 3) == 0) gbuf[w][slot[r]] = dv;
        }
        __syncwarp();

        // softmax over j for the 4 p's (octet-local)
        {
            float lg[2];
            float mx = -1e30f;
#pragma unroll
            for (int i = 0; i < 2; i++) {
                if (i < nj) {
                    lg[i] = gbuf[w][sm_ps * 10 + k8 + i * 8];
                    mx = fmaxf(mx, lg[i]);
                } else lg[i] = -1e30f;
            }
            mx = fmaxf(mx, __shfl_xor_sync(0xffffffffu, mx, 1));
            mx = fmaxf(mx, __shfl_xor_sync(0xffffffffu, mx, 2));
            mx = fmaxf(mx, __shfl_xor_sync(0xffffffffu, mx, 4));
            float e[2], sm = 0.f;
#pragma unroll
            for (int i = 0; i < 2; i++) {
                e[i] = (i < nj) ? __expf(lg[i] - mx) : 0.f;
                sm += e[i];
            }
            sm += __shfl_xor_sync(0xffffffffu, sm, 1);
            sm += __shfl_xor_sync(0xffffffffu, sm, 2);
            sm += __shfl_xor_sync(0xffffffffu, sm, 4);
            const float inv = __fdividef(1.f, sm);
#pragma unroll
            for (int i = 0; i < 2; i++)
                if (i < nj) cbuf[w][sm_ps * 10 + k8 + i * 8] = e[i] * inv;
        }
        __syncwarp();

        // accumulate c * u
#pragma unroll
        for (int r = 0; r < 5; r++) {
            const float c = cbuf[w][slot[r]];
            const __half2* uh2 = (const __half2*)&ucur[r];
            const float2 f0 = __half22float2(uh2[0]);
            const float2 f1 = __half22float2(uh2[1]);
            sacc[r][0] = fmaf(c, f0.x, sacc[r][0]);
            sacc[r][1] = fmaf(c, f0.y, sacc[r][1]);
            sacc[r][2] = fmaf(c, f1.x, sacc[r][2]);
            sacc[r][3] = fmaf(c, f1.y, sacc[r][3]);
        }
        __syncwarp();

#pragma unroll
        for (int r = 0; r < 5; r++) ucur[r] = unxt[r];
    }

    // fold sacc into red[w][jo]: 4 phases by p_sub (conflict-free per phase)
    for (int i = lane; i < JO_; i += 32) red[w][i] = 0.f;
    __syncwarp();
#pragma unroll
    for (int ph = 0; ph < 4; ph++) {
#pragma unroll
        for (int r = 0; r < 5; r++) {
            if (psub[r] == ph) {
#pragma unroll
                for (int k = 0; k < 4; k++) red[w][q[r] + k] += sacc[r][k];
            }
        }
        __syncwarp();
    }
    __syncthreads();

    if (threadIdx.x < JO_) {
        float s = 0.f;
#pragma unroll
        for (int k = 0; k < 8; k++) s += red[k][threadIdx.x];
        atomicAdd(&g_s[SLOT * B_ * JO_ + b * JO_ + threadIdx.x], s);
    }
}

// ---------------------------------------------------------------------------
extern "C" void kernel_launch(void* const* d_in, const int* in_sizes, int n_in,
                              void* d_out, int out_size) {
    const float* x = (const float*)d_in[0];
    const float* W = (const float*)d_in[1];
    if (n_in >= 2 && in_sizes[0] > in_sizes[1]) {
        x = (const float*)d_in[1];
        W = (const float*)d_in[0];
    }
    float* out = (float*)d_out;

    zero_s_kernel<<<60, 256>>>();
    pass0_kernel<<<1024, 256>>>(x, W);
    squash_kernel<<<2, 160>>>(0, nullptr);     // v1 -> g_vh, g_vf
    route_kernel<1><<<2048, 256>>>();          // logits u·v1 -> s2
    squash_kernel<<<2, 160>>>(1, nullptr);     // g_vh = v1+v2
    route_kernel<2><<<2048, 256>>>();          // logits u·(v1+v2) -> s3
    squash_kernel<<<2, 160>>>(2, out);         // v3 -> out
}

// round 6
// speedup vs baseline: 2.2867x; 1.0870x over previous
#include <cuda_runtime.h>
#include <cuda_fp16.h>
#include <math.h>

#define B_  32
#define P_  16384
#define J_  10
#define O_  16
#define JO_ 160

// Scratch (device globals: no allocation allowed in kernel_launch)
__device__ unsigned short g_uh[(size_t)B_ * P_ * JO_]; // 168MB fp16 u_hat[b][p][jo]
__device__ float g_s[3 * B_ * JO_];                    // s accumulators
__device__ float g_vf[B_ * JO_];                       // v1 stash (fp32)
__device__ unsigned short g_vh[B_ * JO_];              // current dot-vector (fp16)

// Packed fp32 FMA (FFMA2): d = a*b + c elementwise, exact fp32 math.
__device__ __forceinline__ float2 ffma2(float2 a, float2 b, float2 c) {
    unsigned long long A = *reinterpret_cast<unsigned long long*>(&a);
    unsigned long long Bv = *reinterpret_cast<unsigned long long*>(&b);
    unsigned long long C = *reinterpret_cast<unsigned long long*>(&c);
    unsigned long long D;
    asm("fma.rn.f32x2 %0, %1, %2, %3;" : "=l"(D) : "l"(A), "l"(Bv), "l"(C));
    return *reinterpret_cast<float2*>(&D);
}
__device__ __forceinline__ float2 dup2(float x) { return make_float2(x, x); }

// ---------------------------------------------------------------------------
__global__ void zero_s_kernel() {
    int i = blockIdx.x * blockDim.x + threadIdx.x;
    if (i < 3 * B_ * JO_) g_s[i] = 0.f;
}

// ---------------------------------------------------------------------------
// Pass 0: u_hat[b,p,jo] = sum_d x[b,p,d] * W[j,p,d,o]   (fp16 out)
// Warp = 8 b (octet) x 2 p per iteration. Lane unit u = r*32+lane in [0,160):
//   psub = u/80 (which p of the pair), h = (2u)%160 = jo-pair base.
// W read as float2 (LDG.64), u stored as half2 (STG.32), FMA via fma.rn.f32x2.
// 4 octet warps share each p-range -> W hits L1. s1 partials in per-warp smem
// slices (float2 ops, 2 psub phases, race-free), folded to global at the end.
// ---------------------------------------------------------------------------
#define NP 8
__global__ __launch_bounds__(256) void pass0_kernel(const float* __restrict__ x,
                                                    const float* __restrict__ W) {
    const int w    = threadIdx.x >> 5;
    const int lane = threadIdx.x & 31;
    const int oct  = w & 3;                      // b-octet
    const int pg   = blockIdx.x * 2 + (w >> 2);  // 2048 p-groups
    const int b0   = oct * 8;
    const int pbase = pg * NP;

    __shared__ float s1sm[8][8 * JO_];           // per-warp slices, 40KB
    float* s1w = s1sm[w];
    for (int i = lane; i < 8 * JO_; i += 32) s1w[i] = 0.f;
    __syncwarp();

    // unit geometry
    int h[5], psub[5];
#pragma unroll
    for (int r = 0; r < 5; r++) {
        const int u = r * 32 + lane;
        psub[r] = (u >= 80) ? 1 : 0;
        h[r]    = (2 * u) % 160;
    }

    __half* uh = reinterpret_cast<__half*>(g_uh);

    for (int it = 0; it < NP / 2; it++) {
        const int p0 = pbase + it * 2;

        // x: lane holds float4 chunk (lane&3) of the 16-float (b, p0..p0+1) strip
        const float4 xq = *(const float4*)(x + ((size_t)(b0 + (lane >> 2)) * P_ + p0) * 8
                                             + (lane & 3) * 4);
        float xe[4] = {xq.x, xq.y, xq.z, xq.w};

        const float2* Wp[5];
#pragma unroll
        for (int r = 0; r < 5; r++)
            Wp[r] = (const float2*)(W + ((size_t)(h[r] >> 4) * P_ + p0 + psub[r]) * 128
                                      + (h[r] & 15));

        float2 acc[8][5];
#pragma unroll
        for (int bb = 0; bb < 8; bb++)
#pragma unroll
            for (int r = 0; r < 5; r++) acc[bb][r] = make_float2(0.f, 0.f);

#pragma unroll
        for (int d = 0; d < 8; d++) {
            float2 wv[5];
#pragma unroll
            for (int r = 0; r < 5; r++) wv[r] = __ldg(Wp[r] + d * 8);

#pragma unroll
            for (int bb = 0; bb < 8; bb++) {
                // x[b0+bb, p0, d] lives in lane bb*4 + (d>>2), elem d&3;
                // x[b0+bb, p0+1, d] in lane bb*4 + 2 + (d>>2), same elem.
                const float xA = __shfl_sync(0xffffffffu, xe[d & 3], bb * 4 + (d >> 2));
                const float xB = __shfl_sync(0xffffffffu, xe[d & 3], bb * 4 + 2 + (d >> 2));
                const float xC = psub[2] ? xB : xA;   // r=2 is lane-dependent
                const float2 xA2 = dup2(xA), xB2 = dup2(xB), xC2 = dup2(xC);
                acc[bb][0] = ffma2(xA2, wv[0], acc[bb][0]);
                acc[bb][1] = ffma2(xA2, wv[1], acc[bb][1]);
                acc[bb][2] = ffma2(xC2, wv[2], acc[bb][2]);
                acc[bb][3] = ffma2(xB2, wv[3], acc[bb][3]);
                acc[bb][4] = ffma2(xB2, wv[4], acc[bb][4]);
            }
        }

        // stores (half2) + s1 smem accumulation (2 race-free psub phases)
#pragma unroll
        for (int bb = 0; bb < 8; bb++) {
#pragma unroll
            for (int r = 0; r < 5; r++) {
                __half2 hv = __float22half2_rn(acc[bb][r]);
                *(__half2*)(uh + ((size_t)(b0 + bb) * P_ + p0 + psub[r]) * JO_ + h[r]) = hv;
            }
        }
#pragma unroll
        for (int ph = 0; ph < 2; ph++) {
#pragma unroll
            for (int r = 0; r < 5; r++) {
                if (psub[r] == ph) {
#pragma unroll
                    for (int bb = 0; bb < 8; bb++) {
                        float2* sp = (float2*)&s1w[bb * JO_ + h[r]];
                        float2 cur = *sp;
                        cur.x += acc[bb][r].x;
                        cur.y += acc[bb][r].y;
                        *sp = cur;
                    }
                }
            }
            __syncwarp();
        }
    }

    __syncthreads();
    // fold the 8 per-warp slices -> global s1 (slot 0), scaled by 1/J
    for (int i = threadIdx.x; i < B_ * JO_; i += 256) {
        const int b  = i / JO_, jo = i % JO_;
        const int o1 = b >> 3, bb = b & 7;
        const float sum = s1sm[o1][bb * JO_ + jo] + s1sm[o1 + 4][bb * JO_ + jo];
        atomicAdd(&g_s[i], sum * 0.1f);
    }
}

// ---------------------------------------------------------------------------
// Squash: v = s * sqrt(|s|^2) / (1 + |s|^2). One thread per (b,j).
// phase 0: v1 -> g_vh (fp16) and g_vf (fp32 stash)
// phase 1: v2 -> g_vh = fp16(v1 + v2)    [logit linearity: b = u·(v1+v2)]
// phase 2: v3 -> d_out (fp32)
// ---------------------------------------------------------------------------
__global__ void squash_kernel(int phase, float* dout) {
    int t = blockIdx.x * blockDim.x + threadIdx.x;
    if (t >= B_ * J_) return;
    const float* sp = g_s + phase * B_ * JO_ + t * O_;
    float sv[16], sq = 0.f;
#pragma unroll
    for (int o = 0; o < 16; o++) { sv[o] = sp[o]; sq += sv[o] * sv[o]; }
    const float scale = sqrtf(sq) / (1.f + sq);
    __half* vh = reinterpret_cast<__half*>(g_vh) + t * O_;
    if (phase == 0) {
#pragma unroll
        for (int o = 0; o < 16; o++) {
            const float v = sv[o] * scale;
            g_vf[t * O_ + o] = v;
            vh[o] = __float2half(v);
        }
    } else if (phase == 1) {
#pragma unroll
        for (int o = 0; o < 16; o++)
            vh[o] = __float2half(g_vf[t * O_ + o] + sv[o] * scale);
    } else {
#pragma unroll
        for (int o = 0; o < 16; o++) dout[t * O_ + o] = sv[o] * scale;
    }
}

// ---------------------------------------------------------------------------
// Fused routing pass: 4 p per iteration, prefetched uint2 (4 fp16) loads.
// Unit u = r*32+lane in [0,160): psub = u/40, slot = u>>2 = psub*10+j.
// Dot: 4-wide fp16 product + 2 shfl quad-reduce. Softmax per octet. No g_b.
// c*u accumulate via fma.rn.f32x2.
// ---------------------------------------------------------------------------
template <int SLOT>
__global__ __launch_bounds__(256) void route_kernel() {
    const int w     = threadIdx.x >> 5;
    const int lane  = threadIdx.x & 31;
    const int gw    = blockIdx.x * 8 + w;     // 16384 warps
    const int b     = gw >> 9;
    const int pbase = (gw & 511) << 5;        // 32 p per warp

    __shared__ float gbuf[8][40];
    __shared__ float cbuf[8][40];
    __shared__ float red[8][JO_];

    uint2 v2[5];
#pragma unroll
    for (int r = 0; r < 5; r++) {
        const int qq = (4 * (r * 32 + lane)) % 160;
        v2[r] = *(const uint2*)(g_vh + b * JO_ + qq);
    }

    float2 sacc[5][2];
#pragma unroll
    for (int r = 0; r < 5; r++) {
        sacc[r][0] = make_float2(0.f, 0.f);
        sacc[r][1] = make_float2(0.f, 0.f);
    }

    const uint2* up = (const uint2*)(g_uh + ((size_t)b * P_ + pbase) * JO_);

    // softmax ownership: octet = p_sub (lane>>3), k8 = lane&7
    const int sm_ps = lane >> 3;
    const int k8    = lane & 7;
    const int nj    = (k8 < 2) ? 2 : 1;       // j in {k8, k8+8?}

    uint2 ucur[5], unxt[5];
#pragma unroll
    for (int r = 0; r < 5; r++) ucur[r] = __ldg(up + r * 32 + lane);

    for (int it = 0; it < 8; it++) {
        if (it < 7) {
#pragma unroll
            for (int r = 0; r < 5; r++)
                unxt[r] = __ldg(up + (it + 1) * 160 + r * 32 + lane);
        }

        // dots: per-unit 4-wide fp16 product, fp32 quad reduction
#pragma unroll
        for (int r = 0; r < 5; r++) {
            const __half2* uh2 = (const __half2*)&ucur[r];
            const __half2* vh2 = (const __half2*)&v2[r];
            const __half2 t = __hfma2(uh2[0], vh2[0], __hmul2(uh2[1], vh2[1]));
            float dv = __low2float(t) + __high2float(t);
            dv += __shfl_xor_sync(0xffffffffu, dv, 1);
            dv += __shfl_xor_sync(0xffffffffu, dv, 2);
            if ((lane & 3) == 0) gbuf[w][r * 8 + (lane >> 2)] = dv;
        }
        __syncwarp();

        // softmax over j for the 4 p's (octet-local)
        {
            float lg[2];
            float mx = -1e30f;
#pragma unroll
            for (int i = 0; i < 2; i++) {
                if (i < nj) {
                    lg[i] = gbuf[w][sm_ps * 10 + k8 + i * 8];
                    mx = fmaxf(mx, lg[i]);
                } else lg[i] = -1e30f;
            }
            mx = fmaxf(mx, __shfl_xor_sync(0xffffffffu, mx, 1));
            mx = fmaxf(mx, __shfl_xor_sync(0xffffffffu, mx, 2));
            mx = fmaxf(mx, __shfl_xor_sync(0xffffffffu, mx, 4));
            float e[2], sm = 0.f;
#pragma unroll
            for (int i = 0; i < 2; i++) {
                e[i] = (i < nj) ? __expf(lg[i] - mx) : 0.f;
                sm += e[i];
            }
            sm += __shfl_xor_sync(0xffffffffu, sm, 1);
            sm += __shfl_xor_sync(0xffffffffu, sm, 2);
            sm += __shfl_xor_sync(0xffffffffu, sm, 4);
            const float inv = __fdividef(1.f, sm);
#pragma unroll
            for (int i = 0; i < 2; i++)
                if (i < nj) cbuf[w][sm_ps * 10 + k8 + i * 8] = e[i] * inv;
        }
        __syncwarp();

        // accumulate c * u (packed fp32 FMA)
#pragma unroll
        for (int r = 0; r < 5; r++) {
            const float2 c2 = dup2(cbuf[w][r * 8 + (lane >> 2)]);
            const __half2* uh2 = (const __half2*)&ucur[r];
            sacc[r][0] = ffma2(c2, __half22float2(uh2[0]), sacc[r][0]);
            sacc[r][1] = ffma2(c2, __half22float2(uh2[1]), sacc[r][1]);
        }
        __syncwarp();

#pragma unroll
        for (int r = 0; r < 5; r++) ucur[r] = unxt[r];
    }

    // fold sacc into red[w][jo]: 4 phases by p_sub (conflict-free per phase)
    for (int i = lane; i < JO_; i += 32) red[w][i] = 0.f;
    __syncwarp();
#pragma unroll
    for (int ph = 0; ph < 4; ph++) {
#pragma unroll
        for (int r = 0; r < 5; r++) {
            const int u = r * 32 + lane;
            if (u / 40 == ph) {
                const int qq = (4 * u) % 160;
                red[w][qq + 0] += sacc[r][0].x;
                red[w][qq + 1] += sacc[r][0].y;
                red[w][qq + 2] += sacc[r][1].x;
                red[w][qq + 3] += sacc[r][1].y;
            }
        }
        __syncwarp();
    }
    __syncthreads();

    if (threadIdx.x < JO_) {
        float s = 0.f;
#pragma unroll
        for (int k = 0; k < 8; k++) s += red[k][threadIdx.x];
        atomicAdd(&g_s[SLOT * B_ * JO_ + b * JO_ + threadIdx.x], s);
    }
}

// ---------------------------------------------------------------------------
extern "C" void kernel_launch(void* const* d_in, const int* in_sizes, int n_in,
                              void* d_out, int out_size) {
    const float* x = (const float*)d_in[0];
    const float* W = (const float*)d_in[1];
    if (n_in >= 2 && in_sizes[0] > in_sizes[1]) {
        x = (const float*)d_in[1];
        W = (const float*)d_in[0];
    }
    float* out = (float*)d_out;

    zero_s_kernel<<<60, 256>>>();
    pass0_kernel<<<1024, 256>>>(x, W);
    squash_kernel<<<2, 160>>>(0, nullptr);     // v1 -> g_vh, g_vf
    route_kernel<1><<<2048, 256>>>();          // logits u·v1 -> s2
    squash_kernel<<<2, 160>>>(1, nullptr);     // g_vh = v1+v2
    route_kernel<2><<<2048, 256>>>();          // logits u·(v1+v2) -> s3
    squash_kernel<<<2, 160>>>(2, out);         // v3 -> out
}